// round 9
// baseline (speedup 1.0000x reference)
#include <cuda_runtime.h>

// CRF loss, T=512, B=1024, K=48. One warp per batch element (grid 1024, one
// wave), length-balancing permutation pre-pass. R9: the forward recursion is
// fully register-resident — the per-step state exchange uses warp shuffles
// (SHFL network, per-SMSP) instead of smem STS/LDS + syncwarp, removing all
// SM-wide smem-crossbar contention from the serial chain. Linear-space
// recursion, exact power-of-2 renorm folded into ex2, 48 fma.rn.f32x2 over
// 8 accumulators.

#define TT 512
#define BB 1024
#define KK 48
#define START_TAG 46
#define STOP_TAG  47
#define LN2F  0.6931471805599453f
#define LOG2E 1.4426950408889634f
#define PFD 6                      // prefetch depth
#define NSM 148

__device__ float g_partial[BB];
__device__ int   g_perm[BB];
__device__ int   g_count = 0;      // last block resets to 0 (graph-replay safe)

__device__ __forceinline__ unsigned long long pack2(float lo, float hi) {
    unsigned long long r;
    asm("mov.b64 %0, {%1, %2};" : "=l"(r) : "f"(lo), "f"(hi));
    return r;
}
__device__ __forceinline__ void unpack2(unsigned long long v, float& lo, float& hi) {
    asm("mov.b64 {%0, %1}, %2;" : "=f"(lo), "=f"(hi) : "l"(v));
}
__device__ __forceinline__ unsigned long long fma2(unsigned long long a,
                                                   unsigned long long b,
                                                   unsigned long long c) {
    unsigned long long d;
    asm("fma.rn.f32x2 %0, %1, %2, %3;" : "=l"(d) : "l"(a), "l"(b), "l"(c));
    return d;
}
__device__ __forceinline__ unsigned long long add2(unsigned long long a,
                                                   unsigned long long b) {
    unsigned long long d;
    asm("add.rn.f32x2 %0, %1, %2;" : "=l"(d) : "l"(a), "l"(b));
    return d;
}
__device__ __forceinline__ float ex2f(float x) {
    float r;
    asm("ex2.approx.f32 %0, %1;" : "=f"(r) : "f"(x));
    return r;
}

// ---------- pre-pass: length-balancing permutation (unchanged from R8) -----
__global__ void perm_kernel(const int* __restrict__ lengths) {
    __shared__ int s_len[BB];
    const int tid = threadIdx.x;
    const int b = blockIdx.x * 512 + tid;
    s_len[tid] = lengths[tid];
    s_len[tid + 512] = lengths[tid + 512];
    __syncthreads();

    const int lb = s_len[b];
    int k = 0;
    #pragma unroll 8
    for (int j = 0; j < BB; j++) {
        int lj = s_len[j];
        k += (lj > lb) || (lj == lb && j < b);
    }
    const int r = k / NSM;
    const int q = k - r * NSM;
    const int g = (r & 1) ? (NSM - 1 - q) : q;
    const unsigned map = (g < 136) ? 0x4562103u : 0x0451023u;
    const int s = (map >> (4 * r)) & 15;
    g_perm[g + NSM * s] = b;
}

// ---------- main recursion: register-resident, shuffle exchange ------------
__global__ void __launch_bounds__(32, 1) crf_kernel(
    const float* __restrict__ feats,
    const float* __restrict__ trans,
    const int*   __restrict__ tags,
    const int*   __restrict__ lengths,
    float*       __restrict__ out)
{
    __shared__ float s_trans[KK * KK];             // prologue/gold only

    const int b    = __ldg(&g_perm[blockIdx.x]);
    const int lane = threadIdx.x;
    const bool act = (lane < 24);
    const int pc = act ? lane : 22;                // clamped pair index
    const int s0 = 2 * pc, s1 = 2 * pc + 1;
    const int len = __ldg(lengths + b);

    for (int i = lane; i < KK * KK; i += 32) s_trans[i] = trans[i];
    __syncwarp();

    // etp0[q] = {exp(T[s0,2q]), exp(T[s0,2q+1])}, etp1 likewise for s1
    unsigned long long etp0[24], etp1[24];
    #pragma unroll
    for (int q = 0; q < 24; q++) {
        etp0[q] = pack2(__expf(s_trans[s0 * KK + 2*q]),
                        __expf(s_trans[s0 * KK + 2*q + 1]));
        etp1[q] = pack2(__expf(s_trans[s1 * KK + 2*q]),
                        __expf(s_trans[s1 * KK + 2*q + 1]));   // exp(-1e4)=0
    }

    const float* fb = feats + b * KK;
    const size_t FS = (size_t)BB * KK;             // floats per time step

    // raw-feat prefetch pipeline, depth 6; running pointer
    float2 r1 = {0,0}, r2 = {0,0}, r3 = {0,0}, r4 = {0,0}, r5 = {0,0}, r6 = {0,0};
    r1 = __ldg((const float2*)(fb + s0));
    if (1 < len) r2 = __ldg((const float2*)(fb + 1 * FS + s0));
    if (2 < len) r3 = __ldg((const float2*)(fb + 2 * FS + s0));
    if (3 < len) r4 = __ldg((const float2*)(fb + 3 * FS + s0));
    if (4 < len) r5 = __ldg((const float2*)(fb + 4 * FS + s0));
    if (5 < len) r6 = __ldg((const float2*)(fb + 5 * FS + s0));
    const float2* pf = (const float2*)(fb + s0) + (size_t)PFD * (FS / 2);
    const int pre = len - PFD;                     // loads valid while t < pre

    // register-resident P: this lane's pair. START=46 lives in pair 23.
    float pl = (lane == 23) ? 1.0f : 0.0f;         // P[2*pc]
    float ph = 0.0f;                               // P[2*pc+1]
    int Cint = 0;

    #pragma unroll 1
    for (int t = 0; t < len; t++) {
        float2 fc = r1;
        r1 = r2; r2 = r3; r3 = r4; r4 = r5; r5 = r6;
        r6 = (t < pre) ? __ldg(pf) : make_float2(0.0f, 0.0f);
        pf += FS / 2;

        unsigned long long c0 = 0ull, c1 = 0ull, c2 = 0ull, c3 = 0ull;
        unsigned long long c4 = 0ull, c5 = 0ull, c6 = 0ull, c7 = 0ull;
        float bl0 = __shfl_sync(~0u, pl, 0);       // P[0] — also renorm source
        #pragma unroll
        for (int q = 0; q < 24; q++) {
            float bl = (q == 0) ? bl0 : __shfl_sync(~0u, pl, q);
            float bh = __shfl_sync(~0u, ph, q);
            unsigned long long bp = pack2(bl, bh); // {P_2q, P_2q+1}
            switch (q & 3) {
                case 0: c0 = fma2(bp, etp0[q], c0);
                        c4 = fma2(bp, etp1[q], c4); break;
                case 1: c1 = fma2(bp, etp0[q], c1);
                        c5 = fma2(bp, etp1[q], c5); break;
                case 2: c2 = fma2(bp, etp0[q], c2);
                        c6 = fma2(bp, etp1[q], c6); break;
                default: c3 = fma2(bp, etp0[q], c3);
                         c7 = fma2(bp, etp1[q], c7); break;
            }
        }
        unsigned long long sum0 = add2(add2(c0, c1), add2(c2, c3));
        unsigned long long sum1 = add2(add2(c4, c5), add2(c6, c7));

        // exact power-of-2 renorm from P[0]'s exponent, folded into ex2
        unsigned int pexp = __float_as_uint(bl0) >> 23;
        int pe = (pexp - 1u < 254u) ? (int)pexp - 127 : 0;
        Cint += pe;
        float fpe = (float)(-pe);
        float m0 = ex2f(fmaf(fc.x, LOG2E, fpe));
        float m1 = ex2f(fmaf(fc.y, LOG2E, fpe));

        float l0, h0, l1, h1;
        unpack2(sum0, l0, h0);
        unpack2(sum1, l1, h1);
        pl = (l0 + h0) * m0;
        ph = (l1 + h1) * m1;
    }

    // log_z = Cint*ln2 + log( sum_j P_j * exp(trans[STOP, j]) )
    float v = 0.0f;
    if (act) {
        v = pl * __expf(s_trans[STOP_TAG * KK + s0])
          + ph * __expf(s_trans[STOP_TAG * KK + s1]);
    }
    #pragma unroll
    for (int o = 16; o; o >>= 1) v += __shfl_xor_sync(~0u, v, o);
    float logz = (float)Cint * LN2F + __logf(v);   // lane 0's Cint valid

    // gold score: strided over t, warp reduce
    const int* tg = tags + b * TT;
    float g = 0.0f;
    for (int q = lane; q < len; q += 32) {
        int nxt = __ldg(tg + q);
        int prv = (q == 0) ? START_TAG : __ldg(tg + q - 1);
        g += s_trans[nxt * KK + prv] + __ldg(fb + (size_t)q * FS + nxt);
    }
    #pragma unroll
    for (int o = 16; o; o >>= 1) g += __shfl_xor_sync(~0u, g, o);

    int last = 0;
    if (lane == 0) {
        float gold = g + s_trans[STOP_TAG * KK + __ldg(tg + len - 1)];
        g_partial[b] = logz - gold;
        __threadfence();
        int prev = atomicAdd(&g_count, 1);
        last = (prev == BB - 1);
    }
    last = __shfl_sync(~0u, last, 0);

    // last block: deterministic fixed-order final reduction, reset counter
    if (last) {
        __threadfence();
        float a = 0.0f;
        #pragma unroll
        for (int i = 0; i < BB / 32; i++)
            a += g_partial[lane + i * 32];
        #pragma unroll
        for (int o = 16; o; o >>= 1) a += __shfl_xor_sync(~0u, a, o);
        if (lane == 0) {
            out[0] = a;
            g_count = 0;                           // replay-safe reset
        }
    }
}

extern "C" void kernel_launch(void* const* d_in, const int* in_sizes, int n_in,
                              void* d_out, int out_size) {
    const float* feats   = (const float*)d_in[0];
    const float* trans   = (const float*)d_in[1];
    const int*   tags    = (const int*)d_in[2];
    const int*   lengths = (const int*)d_in[3];
    perm_kernel<<<2, 512>>>(lengths);
    crf_kernel<<<BB, 32>>>(feats, trans, tags, lengths, (float*)d_out);
}

// round 10
// speedup vs baseline: 1.2792x; 1.2792x over previous
#include <cuda_runtime.h>

// CRF loss, T=512, B=1024, K=48. R10: persistent worker warps (592 blocks x
// 32 threads = 4 warps/SM) popping batch jobs LONGEST-FIRST from an atomic
// queue (LPT scheduling — placement-assumption-free load balance). Step body
// is R8's best: linear-space recursion, smem ping-pong {P_2i,P_2i+1}, one
// broadcast LDS.128 per 4 states, 48 fma.rn.f32x2 over 8 accumulators, exact
// power-of-2 renorm folded into ex2. etp tables + s_trans loaded once per
// worker and reused across jobs.

#define TT 512
#define BB 1024
#define KK 48
#define NWORK 592                  // 4 warps per SM
#define START_TAG 46
#define STOP_TAG  47
#define LN2F  0.6931471805599453f
#define LOG2E 1.4426950408889634f
#define PFD 6                      // prefetch depth

__device__ float g_partial[BB];
__device__ int   g_order[BB];      // rank -> batch (longest first)
__device__ int   g_next;           // job queue head (reset by perm_kernel)
__device__ int   g_done;           // completed jobs (reset by perm_kernel)

__device__ __forceinline__ unsigned long long pack2(float lo, float hi) {
    unsigned long long r;
    asm("mov.b64 %0, {%1, %2};" : "=l"(r) : "f"(lo), "f"(hi));
    return r;
}
__device__ __forceinline__ void unpack2(unsigned long long v, float& lo, float& hi) {
    asm("mov.b64 {%0, %1}, %2;" : "=f"(lo), "=f"(hi) : "l"(v));
}
__device__ __forceinline__ unsigned long long fma2(unsigned long long a,
                                                   unsigned long long b,
                                                   unsigned long long c) {
    unsigned long long d;
    asm("fma.rn.f32x2 %0, %1, %2, %3;" : "=l"(d) : "l"(a), "l"(b), "l"(c));
    return d;
}
__device__ __forceinline__ unsigned long long add2(unsigned long long a,
                                                   unsigned long long b) {
    unsigned long long d;
    asm("add.rn.f32x2 %0, %1, %2;" : "=l"(d) : "l"(a), "l"(b));
    return d;
}
__device__ __forceinline__ float ex2f(float x) {
    float r;
    asm("ex2.approx.f32 %0, %1;" : "=f"(r) : "f"(x));
    return r;
}

// ---------- pre-pass: longest-first rank + counter reset -------------------
__global__ void perm_kernel(const int* __restrict__ lengths) {
    __shared__ int s_len[BB];
    const int tid = threadIdx.x;
    const int b = blockIdx.x * 512 + tid;
    s_len[tid] = lengths[tid];
    s_len[tid + 512] = lengths[tid + 512];
    __syncthreads();

    const int lb = s_len[b];
    int k = 0;
    #pragma unroll 8
    for (int j = 0; j < BB; j++) {
        int lj = s_len[j];
        k += (lj > lb) || (lj == lb && j < b);
    }
    g_order[k] = b;                                 // rank 0 = longest
    if (b == 0) { g_next = 0; g_done = 0; }         // graph-replay safe reset
}

// ---------- one recursion step (R8 body) -----------------------------------
#define STEP(PIN, POUT, FC, RENORM)                                          \
    do {                                                                     \
        const ulonglong2* pv = (const ulonglong2*)(PIN);                     \
        ulonglong2 e0 = pv[0];                                               \
        unsigned long long c0 = fma2(e0.x, etp0[0], 0ull);                   \
        unsigned long long c2 = fma2(e0.y, etp0[1], 0ull);                   \
        unsigned long long c4 = fma2(e0.x, etp1[0], 0ull);                   \
        unsigned long long c6 = fma2(e0.y, etp1[1], 0ull);                   \
        unsigned long long c1 = 0ull, c3 = 0ull, c5 = 0ull, c7 = 0ull;       \
        _Pragma("unroll")                                                    \
        for (int q = 1; q < 12; q++) {                                       \
            ulonglong2 e = pv[q];                                            \
            if (q & 1) {                                                     \
                c1 = fma2(e.x, etp0[2*q],     c1);                           \
                c3 = fma2(e.y, etp0[2*q + 1], c3);                           \
                c5 = fma2(e.x, etp1[2*q],     c5);                           \
                c7 = fma2(e.y, etp1[2*q + 1], c7);                           \
            } else {                                                         \
                c0 = fma2(e.x, etp0[2*q],     c0);                           \
                c2 = fma2(e.y, etp0[2*q + 1], c2);                           \
                c4 = fma2(e.x, etp1[2*q],     c4);                           \
                c6 = fma2(e.y, etp1[2*q + 1], c6);                           \
            }                                                                \
        }                                                                    \
        unsigned long long sum0 = add2(add2(c0, c1), add2(c2, c3));          \
        unsigned long long sum1 = add2(add2(c4, c5), add2(c6, c7));          \
        float fpe = 0.0f;                                                    \
        if (RENORM) {                                                        \
            unsigned int pexp = ((unsigned)e0.x) >> 23;                      \
            int pe = (pexp - 1u < 254u) ? (int)pexp - 127 : 0;               \
            Cint += pe;                                                      \
            fpe = (float)(-pe);                                              \
        }                                                                    \
        float m0 = ex2f(fmaf((FC).x, LOG2E, fpe));                           \
        float m1 = ex2f(fmaf((FC).y, LOG2E, fpe));                           \
        float l0, h0, l1, h1;                                                \
        unpack2(sum0, l0, h0);                                               \
        unpack2(sum1, l1, h1);                                               \
        (POUT)[lane] = make_float2((l0 + h0) * m0, (l1 + h1) * m1);          \
    } while (0)

__global__ void __launch_bounds__(32, 4) crf_kernel(
    const float* __restrict__ feats,
    const float* __restrict__ trans,
    const int*   __restrict__ tags,
    const int*   __restrict__ lengths,
    float*       __restrict__ out)
{
    __shared__ __align__(16) float2 s_p[2][32];    // pairs; 24..31 are pads
    __shared__ float s_trans[KK * KK];

    const int lane = threadIdx.x;
    const bool act = (lane < 24);
    const int sc = act ? 2 * lane : 44;            // clamped state index
    const int s0 = sc, s1 = sc + 1;

    // per-worker prologue (amortized over all jobs this worker runs)
    for (int i = lane; i < KK * KK; i += 32) s_trans[i] = trans[i];
    __syncwarp();

    unsigned long long etp0[24], etp1[24];
    #pragma unroll
    for (int i = 0; i < 24; i++) {
        etp0[i] = pack2(__expf(s_trans[s0 * KK + 2*i]),
                        __expf(s_trans[s0 * KK + 2*i + 1]));
        etp1[i] = pack2(__expf(s_trans[s1 * KK + 2*i]),
                        __expf(s_trans[s1 * KK + 2*i + 1]));   // exp(-1e4)=0
    }
    const float eS0 = __expf(s_trans[STOP_TAG * KK + s0]);
    const float eS1 = __expf(s_trans[STOP_TAG * KK + s1]);
    const size_t FS = (size_t)BB * KK;             // floats per time step

    // ---------------- job loop ----------------
    for (;;) {
        int j = 0;
        if (lane == 0) j = atomicAdd(&g_next, 1);
        j = __shfl_sync(~0u, j, 0);
        if (j >= BB) break;
        const int b   = __ldg(&g_order[j]);
        const int len = __ldg(lengths + b);
        const float* fb = feats + b * KK;

        {
            float2 z = make_float2(0.0f, 0.0f);
            s_p[0][lane] = (lane == 23) ? make_float2(1.0f, 0.0f) : z; // START
            s_p[1][lane] = z;
        }

        // raw-feat prefetch pipeline, depth 6; running pointer
        float2 r1, r2 = {0,0}, r3 = {0,0}, r4 = {0,0}, r5 = {0,0}, r6 = {0,0};
        r1 = __ldg((const float2*)(fb + sc));
        if (1 < len) r2 = __ldg((const float2*)(fb + 1 * FS + sc));
        if (2 < len) r3 = __ldg((const float2*)(fb + 2 * FS + sc));
        if (3 < len) r4 = __ldg((const float2*)(fb + 3 * FS + sc));
        if (4 < len) r5 = __ldg((const float2*)(fb + 4 * FS + sc));
        if (5 < len) r6 = __ldg((const float2*)(fb + 5 * FS + sc));
        const float2* pf = (const float2*)(fb + sc) + (size_t)PFD * (FS / 2);
        const int pre = len - PFD;

        int Cint = 0;
        __syncwarp();

        int t = 0;
        #pragma unroll 1
        while (t + 1 < len) {
            {   // step A: s_p[0] -> s_p[1], with renorm
                float2 fc = r1;
                r1 = r2; r2 = r3; r3 = r4; r4 = r5; r5 = r6;
                r6 = (t < pre) ? __ldg(pf) : make_float2(0.0f, 0.0f);
                pf += FS / 2;
                STEP(s_p[0], s_p[1], fc, true);
            }
            __syncwarp();
            {   // step B: s_p[1] -> s_p[0], no renorm (range-safe)
                float2 fc = r1;
                r1 = r2; r2 = r3; r3 = r4; r4 = r5; r5 = r6;
                r6 = (t + 1 < pre) ? __ldg(pf) : make_float2(0.0f, 0.0f);
                pf += FS / 2;
                STEP(s_p[1], s_p[0], fc, false);
            }
            __syncwarp();
            t += 2;
        }
        if (t < len) {                             // odd tail step
            float2 fc = r1;
            STEP(s_p[0], s_p[1], fc, true);
            __syncwarp();
        }

        // log_z
        float v = 0.0f;
        if (act) {
            float2 P = s_p[len & 1][lane];
            v = P.x * eS0 + P.y * eS1;
        }
        #pragma unroll
        for (int o = 16; o; o >>= 1) v += __shfl_xor_sync(~0u, v, o);
        float logz = (float)Cint * LN2F + __logf(v);

        // gold score
        const int* tg = tags + b * TT;
        float g = 0.0f;
        for (int q = lane; q < len; q += 32) {
            int nxt = __ldg(tg + q);
            int prv = (q == 0) ? START_TAG : __ldg(tg + q - 1);
            g += s_trans[nxt * KK + prv] + __ldg(fb + (size_t)q * FS + nxt);
        }
        #pragma unroll
        for (int o = 16; o; o >>= 1) g += __shfl_xor_sync(~0u, g, o);

        int last = 0;
        if (lane == 0) {
            float gold = g + s_trans[STOP_TAG * KK + __ldg(tg + len - 1)];
            g_partial[b] = logz - gold;
            __threadfence();
            int prev = atomicAdd(&g_done, 1);
            last = (prev == BB - 1);
        }
        last = __shfl_sync(~0u, last, 0);

        if (last) {                                // final fixed-order reduce
            __threadfence();
            float a = 0.0f;
            #pragma unroll
            for (int i = 0; i < BB / 32; i++)
                a += g_partial[lane + i * 32];
            #pragma unroll
            for (int o = 16; o; o >>= 1) a += __shfl_xor_sync(~0u, a, o);
            if (lane == 0) out[0] = a;
        }
    }
}

extern "C" void kernel_launch(void* const* d_in, const int* in_sizes, int n_in,
                              void* d_out, int out_size) {
    const float* feats   = (const float*)d_in[0];
    const float* trans   = (const float*)d_in[1];
    const int*   tags    = (const int*)d_in[2];
    const int*   lengths = (const int*)d_in[3];
    perm_kernel<<<2, 512>>>(lengths);
    crf_kernel<<<NWORK, 32>>>(feats, trans, tags, lengths, (float*)d_out);
}

// round 11
// speedup vs baseline: 1.6420x; 1.2837x over previous
#include <cuda_runtime.h>

// CRF loss, T=512, B=1024, K=48. R11: forward/backward split halves serial
// depth. logZ = log(sum_j alphaF[m-1][j] * betaB[m-1][j]), m = len/2.
// Backward recursion W <- ef (.) (E^T W) has the SAME step structure as
// forward (store ef-multiplied vector), just a transposed weight table.
// 296 blocks x 128 threads: warps 0-1 = fwd workers, warps 2-3 = bwd workers
// (1184 warps, 2 per SMSP guaranteed by wid%4). LPT job queues (2048 jobs of
// <=256 steps). Step body = R8: linear space, smem ping-pong {P_2i,P_2i+1},
// 48 fma.rn.f32x2 / 8 accumulators, exact power-of-2 renorm every 2 steps
// folded into ex2. Per-batch atomic flag: second finisher combines halves.

#define TT 512
#define BB 1024
#define KK 48
#define NBLKW 296
#define START_TAG 46
#define STOP_TAG  47
#define LN2F  0.6931471805599453f
#define LOG2E 1.4426950408889634f
#define PFD 6

__device__ float g_partial[BB];
__device__ float g_fwdv[BB * KK];
__device__ float g_bwdv[BB * KK];
__device__ float g_gold[BB];
__device__ int   g_cf[BB];
__device__ int   g_cb[BB];
__device__ int   g_flag[BB];
__device__ int   g_order[BB];      // rank -> batch (longest first)
__device__ int   g_next_f, g_next_b, g_done;

__device__ __forceinline__ unsigned long long pack2(float lo, float hi) {
    unsigned long long r;
    asm("mov.b64 %0, {%1, %2};" : "=l"(r) : "f"(lo), "f"(hi));
    return r;
}
__device__ __forceinline__ void unpack2(unsigned long long v, float& lo, float& hi) {
    asm("mov.b64 {%0, %1}, %2;" : "=f"(lo), "=f"(hi) : "l"(v));
}
__device__ __forceinline__ unsigned long long fma2(unsigned long long a,
                                                   unsigned long long b,
                                                   unsigned long long c) {
    unsigned long long d;
    asm("fma.rn.f32x2 %0, %1, %2, %3;" : "=l"(d) : "l"(a), "l"(b), "l"(c));
    return d;
}
__device__ __forceinline__ unsigned long long add2(unsigned long long a,
                                                   unsigned long long b) {
    unsigned long long d;
    asm("add.rn.f32x2 %0, %1, %2;" : "=l"(d) : "l"(a), "l"(b));
    return d;
}
__device__ __forceinline__ float ex2f(float x) {
    float r;
    asm("ex2.approx.f32 %0, %1;" : "=f"(r) : "f"(x));
    return r;
}

// ---------- pre-pass: longest-first rank + counter/flag reset --------------
__global__ void perm_kernel(const int* __restrict__ lengths) {
    __shared__ int s_len[BB];
    const int tid = threadIdx.x;
    const int b = blockIdx.x * 512 + tid;
    s_len[tid] = lengths[tid];
    s_len[tid + 512] = lengths[tid + 512];
    __syncthreads();

    const int lb = s_len[b];
    int k = 0;
    #pragma unroll 8
    for (int j = 0; j < BB; j++) {
        int lj = s_len[j];
        k += (lj > lb) || (lj == lb && j < b);
    }
    g_order[k] = b;
    g_flag[b] = 0;
    if (b == 0) { g_next_f = 0; g_next_b = 0; g_done = 0; }
}

// ---------- one recursion step (R8 body) -----------------------------------
#define STEP(PIN, POUT, FC, RENORM)                                          \
    do {                                                                     \
        const ulonglong2* pv = (const ulonglong2*)(PIN);                     \
        ulonglong2 e0 = pv[0];                                               \
        unsigned long long c0 = fma2(e0.x, etp0[0], 0ull);                   \
        unsigned long long c2 = fma2(e0.y, etp0[1], 0ull);                   \
        unsigned long long c4 = fma2(e0.x, etp1[0], 0ull);                   \
        unsigned long long c6 = fma2(e0.y, etp1[1], 0ull);                   \
        unsigned long long c1 = 0ull, c3 = 0ull, c5 = 0ull, c7 = 0ull;       \
        _Pragma("unroll")                                                    \
        for (int q = 1; q < 12; q++) {                                       \
            ulonglong2 e = pv[q];                                            \
            if (q & 1) {                                                     \
                c1 = fma2(e.x, etp0[2*q],     c1);                           \
                c3 = fma2(e.y, etp0[2*q + 1], c3);                           \
                c5 = fma2(e.x, etp1[2*q],     c5);                           \
                c7 = fma2(e.y, etp1[2*q + 1], c7);                           \
            } else {                                                         \
                c0 = fma2(e.x, etp0[2*q],     c0);                           \
                c2 = fma2(e.y, etp0[2*q + 1], c2);                           \
                c4 = fma2(e.x, etp1[2*q],     c4);                           \
                c6 = fma2(e.y, etp1[2*q + 1], c6);                           \
            }                                                                \
        }                                                                    \
        unsigned long long sum0 = add2(add2(c0, c1), add2(c2, c3));          \
        unsigned long long sum1 = add2(add2(c4, c5), add2(c6, c7));          \
        float fpe = 0.0f;                                                    \
        if (RENORM) {                                                        \
            unsigned int pexp = ((unsigned)e0.x) >> 23;                      \
            int pe = (pexp - 1u < 254u) ? (int)pexp - 127 : 0;               \
            Cint += pe;                                                      \
            fpe = (float)(-pe);                                              \
        }                                                                    \
        float m0 = ex2f(fmaf((FC).x, LOG2E, fpe));                           \
        float m1 = ex2f(fmaf((FC).y, LOG2E, fpe));                           \
        float l0, h0, l1, h1;                                                \
        unpack2(sum0, l0, h0);                                               \
        unpack2(sum1, l1, h1);                                               \
        (POUT)[lane] = make_float2((l0 + h0) * m0, (l1 + h1) * m1);          \
    } while (0)

// run N steps of the recursion over s_p ping-pong; result in s_p[N & 1]
#define RUNLOOP(NSTEPS)                                                      \
    do {                                                                     \
        int t = 0;                                                           \
        _Pragma("unroll 1")                                                  \
        while (t + 1 < (NSTEPS)) {                                           \
            {                                                                \
                float2 fc = r1;                                              \
                r1 = r2; r2 = r3; r3 = r4; r4 = r5; r5 = r6;                 \
                r6 = (t < pre) ? __ldg(pf) : make_float2(0.0f, 0.0f);        \
                pf += pstep;                                                 \
                STEP(s_p[0], s_p[1], fc, true);                              \
            }                                                                \
            __syncwarp();                                                    \
            {                                                                \
                float2 fc = r1;                                              \
                r1 = r2; r2 = r3; r3 = r4; r4 = r5; r5 = r6;                 \
                r6 = (t + 1 < pre) ? __ldg(pf) : make_float2(0.0f, 0.0f);    \
                pf += pstep;                                                 \
                STEP(s_p[1], s_p[0], fc, false);                             \
            }                                                                \
            __syncwarp();                                                    \
            t += 2;                                                          \
        }                                                                    \
        if (t < (NSTEPS)) {                                                  \
            float2 fc = r1;                                                  \
            STEP(s_p[0], s_p[1], fc, true);                                  \
            __syncwarp();                                                    \
        }                                                                    \
    } while (0)

// second finisher: combine halves; last batch does the final fixed-order sum
#define COMBINE(BATCH)                                                       \
    do {                                                                     \
        __threadfence();                                                     \
        float v = 0.0f;                                                      \
        if (act) {                                                           \
            float2 pfv = *(const float2*)&g_fwdv[(BATCH) * KK + sc];         \
            float2 bbv = *(const float2*)&g_bwdv[(BATCH) * KK + sc];         \
            v = pfv.x * bbv.x + pfv.y * bbv.y;                               \
        }                                                                    \
        _Pragma("unroll")                                                    \
        for (int o = 16; o; o >>= 1) v += __shfl_xor_sync(~0u, v, o);        \
        float logz = (float)(g_cf[BATCH] + g_cb[BATCH]) * LN2F + __logf(v);  \
        int l2 = 0;                                                          \
        if (lane == 0) {                                                     \
            g_partial[BATCH] = logz - g_gold[BATCH];                         \
            __threadfence();                                                 \
            int p2 = atomicAdd(&g_done, 1);                                  \
            l2 = (p2 == BB - 1);                                             \
        }                                                                    \
        l2 = __shfl_sync(~0u, l2, 0);                                        \
        if (l2) {                                                            \
            __threadfence();                                                 \
            float a = 0.0f;                                                  \
            _Pragma("unroll")                                                \
            for (int i = 0; i < BB / 32; i++)                                \
                a += g_partial[lane + i * 32];                               \
            _Pragma("unroll")                                                \
            for (int o = 16; o; o >>= 1) a += __shfl_xor_sync(~0u, a, o);    \
            if (lane == 0) out[0] = a;                                       \
        }                                                                    \
    } while (0)

__global__ void __launch_bounds__(128, 2) crf_kernel(
    const float* __restrict__ feats,
    const float* __restrict__ trans,
    const int*   __restrict__ tags,
    const int*   __restrict__ lengths,
    float*       __restrict__ out)
{
    __shared__ __align__(16) float2 s_pw[4][2][32];
    __shared__ float s_trans[KK * KK];

    const int tid  = threadIdx.x;
    const int wid  = tid >> 5;
    const int lane = tid & 31;
    const bool act = (lane < 24);
    const int sc = act ? 2 * lane : 44;
    const int s0 = sc, s1 = sc + 1;
    const bool is_fwd = (wid < 2);

    for (int i = tid; i < KK * KK; i += 128) s_trans[i] = trans[i];
    __syncthreads();

    float2 (*s_p)[32] = s_pw[wid];

    // weight tables: fwd = rows of exp(T); bwd = columns (E^T rows)
    unsigned long long etp0[24], etp1[24];
    #pragma unroll
    for (int i = 0; i < 24; i++) {
        if (is_fwd) {
            etp0[i] = pack2(__expf(s_trans[s0 * KK + 2*i]),
                            __expf(s_trans[s0 * KK + 2*i + 1]));
            etp1[i] = pack2(__expf(s_trans[s1 * KK + 2*i]),
                            __expf(s_trans[s1 * KK + 2*i + 1]));
        } else {
            etp0[i] = pack2(__expf(s_trans[(2*i) * KK + s0]),
                            __expf(s_trans[(2*i + 1) * KK + s0]));
            etp1[i] = pack2(__expf(s_trans[(2*i) * KK + s1]),
                            __expf(s_trans[(2*i + 1) * KK + s1]));
        }
    }
    const float st0 = __expf(s_trans[STOP_TAG * KK + s0]);
    const float st1 = __expf(s_trans[STOP_TAG * KK + s1]);
    const size_t FS = (size_t)BB * KK;
    const long long pstep = (long long)(FS / 2) * (is_fwd ? 1 : -1);

    if (is_fwd) {
        for (;;) {
            int j = 0;
            if (lane == 0) j = atomicAdd(&g_next_f, 1);
            j = __shfl_sync(~0u, j, 0);
            if (j >= BB) break;
            const int b   = __ldg(&g_order[j]);
            const int len = __ldg(lengths + b);
            const int m   = len >> 1;              // forward covers t in [0,m)
            const float* fb = feats + b * KK;

            s_p[0][lane] = (lane == 23) ? make_float2(1.0f, 0.0f)
                                        : make_float2(0.0f, 0.0f);  // START
            s_p[1][lane] = make_float2(0.0f, 0.0f);

            float2 r1, r2 = {0,0}, r3 = {0,0}, r4 = {0,0}, r5 = {0,0}, r6 = {0,0};
            r1 = __ldg((const float2*)(fb + sc));  // t=0 (in-bounds: len>=1)
            if (1 < m) r2 = __ldg((const float2*)(fb + 1 * FS + sc));
            if (2 < m) r3 = __ldg((const float2*)(fb + 2 * FS + sc));
            if (3 < m) r4 = __ldg((const float2*)(fb + 3 * FS + sc));
            if (4 < m) r5 = __ldg((const float2*)(fb + 4 * FS + sc));
            if (5 < m) r6 = __ldg((const float2*)(fb + 5 * FS + sc));
            const float2* pf = (const float2*)(fb + sc) + (long long)PFD * (FS / 2);
            const int pre = m - PFD;
            int Cint = 0;
            __syncwarp();

            RUNLOOP(m);

            if (act)
                *(float2*)&g_fwdv[b * KK + sc] = s_p[m & 1][lane];

            // gold score (full sequence)
            const int* tg = tags + b * TT;
            float g = 0.0f;
            for (int q = lane; q < len; q += 32) {
                int nxt = __ldg(tg + q);
                int prv = (q == 0) ? START_TAG : __ldg(tg + q - 1);
                g += s_trans[nxt * KK + prv] + __ldg(fb + (size_t)q * FS + nxt);
            }
            #pragma unroll
            for (int o = 16; o; o >>= 1) g += __shfl_xor_sync(~0u, g, o);

            int prev = 0;
            if (lane == 0) {
                g_gold[b] = g + s_trans[STOP_TAG * KK + __ldg(tg + len - 1)];
                g_cf[b] = Cint;
                __threadfence();
                prev = atomicAdd(&g_flag[b], 1);
            }
            prev = __shfl_sync(~0u, prev, 0);
            if (prev == 1) COMBINE(b);
        }
    } else {
        for (;;) {
            int j = 0;
            if (lane == 0) j = atomicAdd(&g_next_b, 1);
            j = __shfl_sync(~0u, j, 0);
            if (j >= BB) break;
            const int b   = __ldg(&g_order[j]);
            const int len = __ldg(lengths + b);
            const int m   = len >> 1;
            const int Ksteps = len - m;            // >= 1
            const float* fb = feats + b * KK;

            // init: W_{len-1} = ef_{len-1} (.) exp(trans[STOP, :])
            float2 f0 = __ldg((const float2*)(fb + (size_t)(len - 1) * FS + sc));
            s_p[0][lane] = make_float2(st0 * ex2f(f0.x * LOG2E),
                                       st1 * ex2f(f0.y * LOG2E));
            s_p[1][lane] = make_float2(0.0f, 0.0f);

            // descending prefetch: load i consumes feats[len-2-i], valid i<Ksteps-1
            float2 r1 = {0,0}, r2 = {0,0}, r3 = {0,0}, r4 = {0,0}, r5 = {0,0}, r6 = {0,0};
            const float2* fp2 = (const float2*)(fb + sc);
            if (0 < Ksteps - 1) r1 = __ldg(fp2 + (long long)(len - 2) * (FS / 2));
            if (1 < Ksteps - 1) r2 = __ldg(fp2 + (long long)(len - 3) * (FS / 2));
            if (2 < Ksteps - 1) r3 = __ldg(fp2 + (long long)(len - 4) * (FS / 2));
            if (3 < Ksteps - 1) r4 = __ldg(fp2 + (long long)(len - 5) * (FS / 2));
            if (4 < Ksteps - 1) r5 = __ldg(fp2 + (long long)(len - 6) * (FS / 2));
            if (5 < Ksteps - 1) r6 = __ldg(fp2 + (long long)(len - 7) * (FS / 2));
            const float2* pf = fp2 + (long long)(len - 2 - PFD) * (long long)(FS / 2);
            const int pre = Ksteps - 1 - PFD;
            int Cint = 0;
            __syncwarp();

            RUNLOOP(Ksteps);                       // last step fc=0 -> ef=1

            if (act)
                *(float2*)&g_bwdv[b * KK + sc] = s_p[Ksteps & 1][lane];

            int prev = 0;
            if (lane == 0) {
                g_cb[b] = Cint;
                __threadfence();
                prev = atomicAdd(&g_flag[b], 1);
            }
            prev = __shfl_sync(~0u, prev, 0);
            if (prev == 1) COMBINE(b);
        }
    }
}

extern "C" void kernel_launch(void* const* d_in, const int* in_sizes, int n_in,
                              void* d_out, int out_size) {
    const float* feats   = (const float*)d_in[0];
    const float* trans   = (const float*)d_in[1];
    const int*   tags    = (const int*)d_in[2];
    const int*   lengths = (const int*)d_in[3];
    perm_kernel<<<2, 512>>>(lengths);
    crf_kernel<<<NBLKW, 128>>>(feats, trans, tags, lengths, (float*)d_out);
}